// round 14
// baseline (speedup 1.0000x reference)
#include <cuda_runtime.h>
#include <float.h>

// Problem constants
#define HH 512
#define WW 512
#define MBS 8
#define PR 8
#define NBR 64
#define NBC 64
#define NPAIR 14
#define NBATCH 4
#define CROPX 17
#define OUTD 478
#define LARGEC 65537.0f
#define MAX_STEPS 16

#define WCOLS 80            // window cols per copy
#define WROWS 24
#define WCPY  (WROWS * WCOLS)   // 1920 floats per parity copy

typedef unsigned long long ull;

__device__ int2 g_motion[NBATCH * NPAIR * NBR * NBC];

// LDSP points as (dx, dy) matching reference ordering; cost uses (y+dy, x+dx).
__constant__ int c_ldsp_dx[9] = { 0, -1, 1, -2, 0, 2, -1, 1, 0 };
__constant__ int c_ldsp_dy[9] = { -2, -1, -1, 0, 0, 0, 1, 1, 2 };
__constant__ int c_sdsp_dx[5] = { 0, -1, 0, 1, 0 };
__constant__ int c_sdsp_dy[5] = { -1, 0, 0, 0, 1 };

// Packed fp32x2 add (sm_103a): rounding identical to scalar FADD per lane.
__device__ __forceinline__ ull addp(ull a, ull b) {
    ull d;
    asm("add.rn.f32x2 %0, %1, %2;" : "=l"(d) : "l"(a), "l"(b));
    return d;
}
// Packed abs: clear both sign bits (bit-exact |x|); ALU pipe.
__device__ __forceinline__ ull absp(ull a) {
    ull d;
    asm("and.b64 %0, %1, 0x7FFFFFFF7FFFFFFF;" : "=l"(d) : "l"(a));
    return d;
}

// First-index argmin over a 16-lane group. Costs >= 0 so u32 order on the bit
// patterns == float order; idle lanes pass FLT_MAX. Lowest matching lane ==
// jnp.argmin first-index (lane-in-group is candidate index).
__device__ __forceinline__ int argmin16(float v, unsigned gmask, int base) {
    unsigned bits = __float_as_uint(v);
    unsigned mn;
    asm("redux.sync.min.u32 %0, %1, %2;" : "=r"(mn) : "r"(bits), "r"(gmask));
    unsigned bal = __ballot_sync(gmask, bits == mn);
    return __ffs(bal >> base) - 1;
}

// One CTA: 8 macroblocks. 128 threads = 8 groups of 16 lanes.
// Lanes 0-8: LDSP candidates; lanes 9-13: speculative SDSP at the center
// (valid when the loop exits with pt==4). SAD accumulation replicates XLA GPU's
// row-reduction association (pacc[t]=|d|[t]+|d|[t+32], tree 16/8/4/2/1) —
// bit-exact argmin vs the reference.
// Window stored NEGATED in FOUR parity-shifted copies (copy s = window shifted
// left by s cols) so every candidate offset reads 16B-aligned LDS.128:
// shared-memory ops per eval drop 64 -> 32 (LSU/MIO issue is the suspected
// binding resource). Block rows are naturally 16B-aligned broadcasts.
__global__ __launch_bounds__(128) void motion_kernel(const float* __restrict__ x) {
    __shared__ __align__(16) float swc [4 * WCPY];  // 4 parity copies of -window
    __shared__ __align__(16) float sblk[8 * 64];

    const int jt  = blockIdx.x;
    const int bi  = blockIdx.y;
    const int bp_ = blockIdx.z;              // b*NPAIR + p
    const int b   = bp_ / NPAIR;
    const int p   = bp_ % NPAIR;

    const float* imgI = x + (size_t)(b * 16 + p) * HH * WW;
    const float* imgP = imgI + (size_t)HH * WW;

    const int i  = bi * MBS;
    const int j0 = jt * 64;
    const int tid = threadIdx.x;

    // Window fill: rows [i-8,i+16), cols [j0-8,j0+72), clamped (clamped cells
    // only ever back invalid, predicated-off candidates). Each value lands in
    // all 4 parity copies (copy s holds win shifted left by s).
    for (int t = tid; t < WROWS * WCOLS; t += 128) {
        int r = t / WCOLS, c = t - r * WCOLS;
        int gr = i - 8 + r;  gr = gr < 0 ? 0 : (gr > HH - 1 ? HH - 1 : gr);
        int gc = j0 - 8 + c; gc = gc < 0 ? 0 : (gc > WW - 1 ? WW - 1 : gc);
        float v = -imgI[gr * WW + gc];               // negated for packed-add subtraction
        int rb = r * WCOLS;
        swc[rb + c] = v;
        if (c >= 1) swc[WCPY     + rb + c - 1] = v;
        if (c >= 2) swc[2 * WCPY + rb + c - 2] = v;
        if (c >= 3) swc[3 * WCPY + rb + c - 3] = v;
    }
    for (int t = tid; t < 8 * 64; t += 128) {
        int r = t >> 6, c = t & 63;
        sblk[t] = imgP[(i + r) * WW + (j0 + c)];
    }
    __syncthreads();

    const int g  = tid >> 4;
    const int lg = tid & 15;
    const int base16 = tid & 16;
    const unsigned gmask = 0xFFFFu << base16;
    const int j = j0 + g * 8;
    const float* bb = sblk + g * 8;

    // SAD mean, XLA association, all shared reads as LDS.128.
    auto evalc = [&](int cy, int cx) -> float {
        const int row = cy - i + 8;
        const int o   = cx - j0 + 8;            // 0..72 for valid candidates
        const float* wp = swc + (o & 3) * WCPY + row * WCOLS + (o & ~3);
        ull pk[16];
#pragma unroll
        for (int r0 = 0; r0 < 4; r0++) {
            ulonglong2 wl  = *(const ulonglong2*)(wp + r0 * WCOLS);
            ulonglong2 wh  = *(const ulonglong2*)(wp + r0 * WCOLS + 4);
            ulonglong2 wl4 = *(const ulonglong2*)(wp + (r0 + 4) * WCOLS);
            ulonglong2 wh4 = *(const ulonglong2*)(wp + (r0 + 4) * WCOLS + 4);
            ulonglong2 bl  = *(const ulonglong2*)(bb + r0 * 64);
            ulonglong2 bh  = *(const ulonglong2*)(bb + r0 * 64 + 4);
            ulonglong2 bl4 = *(const ulonglong2*)(bb + (r0 + 4) * 64);
            ulonglong2 bh4 = *(const ulonglong2*)(bb + (r0 + 4) * 64 + 4);
            // pacc[t], pacc[t+1] for t = 8*r0 + {0,2,4,6}; partner rows r0+4.
            pk[4 * r0 + 0] = addp(absp(addp(bl.x, wl.x)), absp(addp(bl4.x, wl4.x)));
            pk[4 * r0 + 1] = addp(absp(addp(bl.y, wl.y)), absp(addp(bl4.y, wl4.y)));
            pk[4 * r0 + 2] = addp(absp(addp(bh.x, wh.x)), absp(addp(bh4.x, wh4.x)));
            pk[4 * r0 + 3] = addp(absp(addp(bh.y, wh.y)), absp(addp(bh4.y, wh4.y)));
        }
        // Scalar tree offsets 16,8,4,2 == packed offsets 8,4,2,1 (elementwise).
#pragma unroll
        for (int off = 8; off >= 1; off >>= 1)
#pragma unroll
            for (int u = 0; u < 8; u++)
                if (u < off) pk[u] = addp(pk[u], pk[u + off]);
        float lo, hi;
        asm("mov.b64 {%0, %1}, %2;" : "=f"(lo), "=f"(hi) : "l"(pk[0]));
        return (lo + hi) * 0.015625f;
    };

    auto costat = [&](int cy, int cx) -> float {
        bool valid = (cy >= 0) && (cy + MBS <= HH) && (cx >= 0) && (cx + MBS <= WW)
                   && (cy - i <= PR) && (i - cy <= PR) && (cx - j <= PR) && (j - cx <= PR);
        float cst = LARGEC;
        if (valid) cst = evalc(cy, cx);
        return cst;
    };

    // Lane role: 0-8 LDSP, 9-13 SDSP(lg-9), 14-15 dup SDSP center.
    const bool isldsp = (lg < 9);
    const int  sdi    = (lg >= 9 && lg < 14) ? (lg - 9) : 2;
    const int  mdy    = isldsp ? c_ldsp_dy[lg] : c_sdsp_dy[sdi];
    const int  mdx    = isldsp ? c_ldsp_dx[lg] : c_sdsp_dx[sdi];

    int y = i, xx = j;
    bool have_sdsp = false;

    for (int k = 0; k < MAX_STEPS; k++) {
        float cost = costat(y + mdy, xx + mdx);

        if (k == 0) {
            // Reference's standalone c0 check == lane 4's cost this round.
            float ctr = __shfl_sync(gmask, cost, 4, 16);
            if (ctr == 0.0f) { have_sdsp = true; break; }
        }

        int idx = argmin16(isldsp ? cost : FLT_MAX, gmask, base16);
        if (idx == 4) { have_sdsp = true; break; }   // center: lanes 9-13 hold SDSP
        y  += c_ldsp_dy[idx];
        xx += c_ldsp_dx[idx];
    }

    // SDSP refinement: speculative costs (lanes 9-13), or fallback recompute.
    {
        int si;
        if (have_sdsp) {
            float v = (lg >= 9 && lg < 14) ? costat(y + mdy, xx + mdx) : FLT_MAX;
            si = argmin16(v, gmask, base16) - 9;      // lane 9..13 -> idx 0..4
        } else {
            float v = (lg < 5) ? costat(y + c_sdsp_dy[lg], xx + c_sdsp_dx[lg]) : FLT_MAX;
            si = argmin16(v, gmask, base16);
        }
        y  += c_sdsp_dy[si];
        xx += c_sdsp_dx[si];
    }

    if (lg == 0) {
        g_motion[(bp_ * NBR + bi) * NBC + (jt * 8 + g)] = make_int2(y - i, xx - j);
    }
}

// Output: first half = target (crop of frame f+2), second half = pred
// (motion-compensated warp of frame f+1 through g_motion, cropped).
// 4 rows per thread -> 8+ independent loads in flight (L2-latency bound).
__global__ void out_kernel(const float* __restrict__ x, float* __restrict__ out) {
    int c = blockIdx.x * blockDim.x + threadIdx.x;
    if (c >= OUTD) return;
    int rb = blockIdx.y * 4;
    int z  = blockIdx.z;
    int b = z / NPAIR;
    int f = z - b * NPAIR;

    const float* base = x + (size_t)b * 16 * HH * WW;
    const float* tgt  = base + (size_t)(f + 2) * HH * WW;
    const float* ref  = base + (size_t)(f + 1) * HH * WW;
    const size_t TOT = (size_t)NBATCH * NPAIR * OUTD * OUTD;
    const int2* mrow = &g_motion[(b * NPAIR + f) * NBR * NBC];

    int C = CROPX + c;
    int cb = C >> 3;

    float t_[4], p_[4];
    int nr = (OUTD - rb) < 4 ? (OUTD - rb) : 4;

#pragma unroll
    for (int u = 0; u < 4; u++) {
        if (u < nr) {
            int R = CROPX + rb + u;
            t_[u] = tgt[(size_t)R * WW + C];
            int2 m = mrow[(R >> 3) * NBC + cb];
            p_[u] = ref[(size_t)(R + m.x) * WW + (C + m.y)];
        }
    }

    size_t o = ((size_t)z * OUTD + rb) * OUTD + c;
#pragma unroll
    for (int u = 0; u < 4; u++) {
        if (u < nr) {
            out[o + (size_t)u * OUTD] = t_[u];
            out[TOT + o + (size_t)u * OUTD] = p_[u];
        }
    }
}

extern "C" void kernel_launch(void* const* d_in, const int* in_sizes, int n_in,
                              void* d_out, int out_size) {
    const float* x = (const float*)d_in[0];
    float* out = (float*)d_out;

    dim3 gm(8, 64, NBATCH * NPAIR);
    motion_kernel<<<gm, 128>>>(x);

    dim3 go((OUTD + 255) / 256, (OUTD + 3) / 4, NBATCH * NPAIR);
    out_kernel<<<go, 256>>>(x, out);
}

// round 17
// speedup vs baseline: 2.2485x; 2.2485x over previous
#include <cuda_runtime.h>
#include <float.h>

// Problem constants
#define HH 512
#define WW 512
#define MBS 8
#define PR 8
#define NBR 64
#define NBC 64
#define NPAIR 14
#define NBATCH 4
#define CROPX 17
#define OUTD 478
#define LARGEC 65537.0f
#define MAX_STEPS 16
#define SW 84              // padded smem window stride (cols)
#define NT (8 * 64 * 56)   // total tiles: jt(8) x bi(64) x bp(56)
#define NCTA 1776          // persistent CTAs (~12/SM)

__device__ int2 g_motion[NBATCH * NPAIR * NBR * NBC];
__device__ unsigned g_ctr;

// LDSP points as (dx, dy) matching reference ordering; cost uses (y+dy, x+dx).
__constant__ int c_ldsp_dx[9] = { 0, -1, 1, -2, 0, 2, -1, 1, 0 };
__constant__ int c_ldsp_dy[9] = { -2, -1, -1, 0, 0, 0, 1, 1, 2 };
__constant__ int c_sdsp_dx[5] = { 0, -1, 0, 1, 0 };
__constant__ int c_sdsp_dy[5] = { -1, 0, 0, 0, 1 };

__device__ __forceinline__ unsigned smem_u32(const void* p) {
    return (unsigned)__cvta_generic_to_shared(p);
}
__device__ __forceinline__ void cpasync16(void* dst, const float* src) {
    asm volatile("cp.async.cg.shared.global [%0], [%1], 16;"
                 :: "r"(smem_u32(dst)), "l"(src));
}

// First-index argmin over a 16-lane group. Costs >= 0 so u32 order on bit
// patterns == float order; idle lanes pass FLT_MAX. Lowest matching lane ==
// jnp.argmin first-index (lane-in-group is candidate index).
__device__ __forceinline__ int argmin16(float v, unsigned gmask, int base) {
    unsigned bits = __float_as_uint(v);
    unsigned mn;
    asm("redux.sync.min.u32 %0, %1, %2;" : "=r"(mn) : "r"(bits), "r"(gmask));
    unsigned bal = __ballot_sync(gmask, bits == mn);
    return __ffs(bal >> base) - 1;
}

__global__ void reset_kernel() { g_ctr = 0; }

// Persistent motion kernel. Each CTA loops over atomic-ticket tiles with a
// double-buffered cp.async pipeline: buffer for tile n+1 fills (LDGSTS,
// register-free) while tile n's diamond search runs. Per 16-lane group:
// lanes 0-8 = LDSP candidates, 9-13 = speculative SDSP at the center (valid
// when the loop exits with pt==4). SAD replicates XLA GPU's row-reduction
// association: pacc[t] = |d|[t] + |d|[t+32], tree offsets 16,8,4,2,1 —
// bit-exact argmin vs the reference.
// Edge tiles: row pointers clamp upward; right/bottom overflow reads stay
// inside x (frames beyond imgI always exist here) and only fill cells that
// are read exclusively by invalid (branch-skipped) candidates; jt==0's two
// leading chunks are skipped (cells unread by valid candidates).
__global__ __launch_bounds__(128) void motion_kernel(const float* __restrict__ x) {
    __shared__ __align__(16) float swin[2][24 * SW];
    __shared__ __align__(16) float sblk[2][8 * 64];
    __shared__ unsigned s_tile[2];

    const int tid = threadIdx.x;

    auto fill = [&](int buf, unsigned tile) {
        int jt = tile & 7, bi = (tile >> 3) & 63, bp = tile >> 9;
        int b = bp / NPAIR, p = bp - b * NPAIR;
        const float* imgI = x + (size_t)(b * 16 + p) * HH * WW;
        const float* imgP = imgI + (size_t)HH * WW;
        int i = bi * MBS, j0 = jt * 64;
        // Window rows [i-8, i+16), cols [j0-8, j0+72): 24 rows x 20 16B-chunks.
        for (int ch = tid; ch < 480; ch += 128) {
            int r = ch / 20, cc = ch - r * 20;
            int col = j0 - 8 + cc * 4;
            if (col < 0) continue;                    // jt==0 leading chunks
            int gr = i - 8 + r; if (gr < 0) gr = 0;   // bottom overflow is legal
            cpasync16(&swin[buf][r * SW + cc * 4], imgI + gr * WW + col);
        }
        // Block 8 rows x 16 chunks = 128 chunks, one per thread.
        {
            int r = tid >> 4, cc = tid & 15;
            cpasync16(&sblk[buf][r * 64 + cc * 4], imgP + (i + r) * WW + j0 + cc * 4);
        }
    };

    // Prologue: two tickets, two fills in flight.
    if (tid == 0) {
        s_tile[0] = atomicAdd(&g_ctr, 1);
        s_tile[1] = atomicAdd(&g_ctr, 1);
    }
    __syncthreads();
    unsigned tiles[2] = { s_tile[0], s_tile[1] };
    if (tiles[0] < NT) fill(0, tiles[0]);
    asm volatile("cp.async.commit_group;");
    if (tiles[1] < NT) fill(1, tiles[1]);
    asm volatile("cp.async.commit_group;");

    const int g  = tid >> 4;
    const int lg = tid & 15;
    const int base16 = tid & 16;
    const unsigned gmask = 0xFFFFu << base16;
    const bool isldsp = (lg < 9);
    const int  sdi    = (lg >= 9 && lg < 14) ? (lg - 9) : 2;
    const int  mdy    = isldsp ? c_ldsp_dy[lg] : c_sdsp_dy[sdi];
    const int  mdx    = isldsp ? c_ldsp_dx[lg] : c_sdsp_dx[sdi];

    int cur = 0;
    while (tiles[cur] < NT) {
        asm volatile("cp.async.wait_group 1;");   // current buffer's fill done
        __syncthreads();

        const unsigned tile = tiles[cur];
        const int jt = tile & 7, bi = (tile >> 3) & 63, bp = tile >> 9;
        const int i = bi * MBS, j0 = jt * 64;
        const int j = j0 + g * 8;
        const float* wbase = swin[cur];
        const float* bb    = sblk[cur] + g * 8;

        // SAD mean, XLA association (measured-best scalar form).
        auto evalc = [&](int cy, int cx) -> float {
            const float* wp = wbase + (cy - i + 8) * SW + (cx - j0 + 8);
            float pacc[32];
#pragma unroll
            for (int tp = 0; tp < 16; tp++) {
                int t  = tp * 2;
                int r0 = t >> 3, c0_ = t & 7;
                int r1 = r0 + 4;
                float2 b0 = *(const float2*)(bb + r0 * 64 + c0_);
                float2 b1 = *(const float2*)(bb + r1 * 64 + c0_);
                float w00 = wp[r0 * SW + c0_], w01 = wp[r0 * SW + c0_ + 1];
                float w10 = wp[r1 * SW + c0_], w11 = wp[r1 * SW + c0_ + 1];
                pacc[t]     = fabsf(b0.x - w00) + fabsf(b1.x - w10);
                pacc[t + 1] = fabsf(b0.y - w01) + fabsf(b1.y - w11);
            }
#pragma unroll
            for (int off = 16; off >= 1; off >>= 1)
#pragma unroll
                for (int t = 0; t < 16; t++)
                    if (t < off) pacc[t] = pacc[t] + pacc[t + off];
            return pacc[0] * 0.015625f;
        };

        auto costat = [&](int cy, int cx) -> float {
            bool valid = (cy >= 0) && (cy + MBS <= HH) && (cx >= 0) && (cx + MBS <= WW)
                       && (cy - i <= PR) && (i - cy <= PR) && (cx - j <= PR) && (j - cx <= PR);
            float cst = LARGEC;
            if (valid) cst = evalc(cy, cx);
            return cst;
        };

        int y = i, xx = j;
        float my_sdsp = FLT_MAX;
        bool have_sdsp = false;

        for (int k = 0; k < MAX_STEPS; k++) {
            float cost = costat(y + mdy, xx + mdx);
            if (lg >= 9) my_sdsp = cost;

            if (k == 0) {
                // Reference's standalone c0 check == lane 4's cost this round.
                float ctr = __shfl_sync(gmask, cost, 4, 16);
                if (ctr == 0.0f) { have_sdsp = true; break; }
            }

            int idx = argmin16(isldsp ? cost : FLT_MAX, gmask, base16);
            if (idx == 4) { have_sdsp = true; break; }   // lanes 9-13 hold SDSP
            y  += c_ldsp_dy[idx];
            xx += c_ldsp_dx[idx];
        }

        {
            int si;
            if (have_sdsp) {
                float v = (lg >= 9 && lg < 14) ? my_sdsp : FLT_MAX;
                si = argmin16(v, gmask, base16) - 9;     // lane 9..13 -> 0..4
            } else {
                float v = (lg < 5) ? costat(y + c_sdsp_dy[lg], xx + c_sdsp_dx[lg]) : FLT_MAX;
                si = argmin16(v, gmask, base16);
            }
            y  += c_sdsp_dy[si];
            xx += c_sdsp_dx[si];
        }

        if (lg == 0) {
            g_motion[(bp * NBR + bi) * NBC + (jt * 8 + g)] = make_int2(y - i, xx - j);
        }

        __syncthreads();                          // all groups done with buf[cur]
        if (tid == 0) s_tile[cur] = atomicAdd(&g_ctr, 1);
        __syncthreads();
        tiles[cur] = s_tile[cur];
        if (tiles[cur] < NT) fill(cur, tiles[cur]);
        asm volatile("cp.async.commit_group;");
        cur ^= 1;
    }
}

// Output: first half = target (crop of frame f+2), second half = pred
// (motion-compensated warp of frame f+1 through g_motion, cropped).
// 4 rows per thread -> 8+ independent loads in flight (L2-latency bound).
__global__ void out_kernel(const float* __restrict__ x, float* __restrict__ out) {
    int c = blockIdx.x * blockDim.x + threadIdx.x;
    if (c >= OUTD) return;
    int rb = blockIdx.y * 4;
    int z  = blockIdx.z;
    int b = z / NPAIR;
    int f = z - b * NPAIR;

    const float* base = x + (size_t)b * 16 * HH * WW;
    const float* tgt  = base + (size_t)(f + 2) * HH * WW;
    const float* ref  = base + (size_t)(f + 1) * HH * WW;
    const size_t TOT = (size_t)NBATCH * NPAIR * OUTD * OUTD;
    const int2* mrow = &g_motion[(b * NPAIR + f) * NBR * NBC];

    int C = CROPX + c;
    int cb = C >> 3;

    float t_[4], p_[4];
    int nr = (OUTD - rb) < 4 ? (OUTD - rb) : 4;

#pragma unroll
    for (int u = 0; u < 4; u++) {
        if (u < nr) {
            int R = CROPX + rb + u;
            t_[u] = tgt[(size_t)R * WW + C];
            int2 m = mrow[(R >> 3) * NBC + cb];
            p_[u] = ref[(size_t)(R + m.x) * WW + (C + m.y)];
        }
    }

    size_t o = ((size_t)z * OUTD + rb) * OUTD + c;
#pragma unroll
    for (int u = 0; u < 4; u++) {
        if (u < nr) {
            out[o + (size_t)u * OUTD] = t_[u];
            out[TOT + o + (size_t)u * OUTD] = p_[u];
        }
    }
}

extern "C" void kernel_launch(void* const* d_in, const int* in_sizes, int n_in,
                              void* d_out, int out_size) {
    const float* x = (const float*)d_in[0];
    float* out = (float*)d_out;

    reset_kernel<<<1, 1>>>();
    motion_kernel<<<NCTA, 128>>>(x);

    dim3 go((OUTD + 255) / 256, (OUTD + 3) / 4, NBATCH * NPAIR);
    out_kernel<<<go, 256>>>(x, out);
}